// round 10
// baseline (speedup 1.0000x reference)
#include <cuda_runtime.h>
#include <math_constants.h>

#define NX   1000
#define NP   1008        // padded shared hist (bin 1000 possible; folded into 999)
#define HB   296         // grid: 2 CTAs/SM x 148 SMs -> ALL resident (barrier-safe)
#define HT   1024
#define HALF (HB / 2)    // blocks [0,148) -> array a, [148,296) -> array b

// ---------------- device-global scratch (zero-init is the neutral state) ----
__device__ unsigned int g_negmin_bits;   // holds max(~enc(v))  -> min value
__device__ unsigned int g_max_bits;      // holds max( enc(v))  -> max value
__device__ unsigned int g_hist[2][NX];
__device__ unsigned int g_bar;           // grid barrier counter
__device__ unsigned int g_ticket;        // last-block detection

__device__ __forceinline__ unsigned int enc_f(float f) {
    unsigned int u = __float_as_uint(f);
    return (u & 0x80000000u) ? ~u : (u | 0x80000000u);
}
__device__ __forceinline__ float dec_f(unsigned int u) {
    u = (u & 0x80000000u) ? (u & 0x7FFFFFFFu) : ~u;
    return __uint_as_float(u);
}

// The linspace grid point, matching f32 "lo + j*step" with exact endpoint.
__device__ __forceinline__ float xval(int j, float lo, float hi, float step) {
    return (j >= NX - 1) ? hi : fmaf((float)j, step, lo);
}

// Cheap bin: ceil_to_int((v-lo)/step), NO clamp — j in [0,1000]; padded
// shared hist absorbs 1000, folded into 999 at flush (exact).
__device__ __forceinline__ int binof(float v, float invstep, float negloinv) {
    return __float2int_ru(fmaf(v, invstep, negloinv));   // F2I.RP
}

__device__ __forceinline__ void mm4(float4 v, float& mn, float& mx) {
    mn = fminf(mn, fminf(fminf(v.x, v.y), fminf(v.z, v.w)));
    mx = fmaxf(mx, fmaxf(fmaxf(v.x, v.y), fmaxf(v.z, v.w)));
}
__device__ __forceinline__ void hist4(float4 v, unsigned int* h,
                                      float invstep, float negloinv) {
    atomicAdd(&h[binof(v.x, invstep, negloinv)], 1u);
    atomicAdd(&h[binof(v.y, invstep, negloinv)], 1u);
    atomicAdd(&h[binof(v.z, invstep, negloinv)], 1u);
    atomicAdd(&h[binof(v.w, invstep, negloinv)], 1u);
}

// =================== single fused persistent kernel =========================
__global__ void __launch_bounds__(HT, 2) crps_k(const float* __restrict__ a,
                                                const float* __restrict__ b,
                                                int n, float* __restrict__ out) {
    __shared__ unsigned int sh[NP];      // this block's histogram
    __shared__ unsigned int sh2[NP];     // finishing block: second CDF
    __shared__ float smn[32], smx[32];
    __shared__ double sd[32];
    __shared__ unsigned int ws0[32], ws1[32];
    __shared__ unsigned int s_last;

    const int t    = threadIdx.x;
    const int bid  = blockIdx.x;
    const int lane = t & 31, w = t >> 5;    // 32 warps

    const int which = (bid < HALF) ? 0 : 1;
    const int vbid  = bid - which * HALF;
    const float* __restrict__ src = which ? b : a;
    const float4* __restrict__ s4 = (const float4*)src;

    const int n4   = n >> 2;
    const int S    = HALF * HT;           // stride within one array's block set
    const int base = vbid * HT + t;

    for (int i = t; i < NP; i += HT) sh[i] = 0u;   // zero hist early

    // ---------------- phase A: min/max over this block's array --------------
    float mn = CUDART_INF_F, mx = -CUDART_INF_F;
    int i = base;
    for (; i + 3 * S < n4; i += 4 * S) {
        float4 v0 = s4[i];
        float4 v1 = s4[i + S];
        float4 v2 = s4[i + 2 * S];
        float4 v3 = s4[i + 3 * S];
        mm4(v0, mn, mx);
        mm4(v1, mn, mx);
        mm4(v2, mn, mx);
        mm4(v3, mn, mx);
    }
    for (; i < n4; i += S) {
        float4 v0 = s4[i];
        mm4(v0, mn, mx);
    }
    if (bid == 0 && t == 0) {            // scalar tail (n % 4), both arrays
        for (int k = (n4 << 2); k < n; ++k) {
            mn = fminf(mn, fminf(a[k], b[k]));
            mx = fmaxf(mx, fmaxf(a[k], b[k]));
        }
    }
    for (int o = 16; o; o >>= 1) {
        mn = fminf(mn, __shfl_xor_sync(0xFFFFFFFFu, mn, o));
        mx = fmaxf(mx, __shfl_xor_sync(0xFFFFFFFFu, mx, o));
    }
    if (lane == 0) { smn[w] = mn; smx[w] = mx; }
    __syncthreads();
    if (t < 32) {
        mn = smn[t];
        mx = smx[t];
        for (int o = 16; o; o >>= 1) {
            mn = fminf(mn, __shfl_xor_sync(0xFFFFFFFFu, mn, o));
            mx = fmaxf(mx, __shfl_xor_sync(0xFFFFFFFFu, mx, o));
        }
        if (t == 0) {
            atomicMax(&g_negmin_bits, ~enc_f(mn));
            atomicMax(&g_max_bits, enc_f(mx));
        }
    }
    __syncthreads();

    // ---------------- grid barrier (all 296 CTAs resident -> safe) ----------
    if (t == 0) {
        __threadfence();
        atomicAdd(&g_bar, 1u);
        while (*((volatile unsigned int*)&g_bar) < HB) __nanosleep(64);
    }
    __syncthreads();
    __threadfence();

    // ---------------- phase B: histogram this block's array -----------------
    float lo = dec_f(~__ldcg(&g_negmin_bits));
    float hi = dec_f(__ldcg(&g_max_bits));
    float step = (hi - lo) / (float)(NX - 1);
    float invstep = (step > 0.0f) ? (1.0f / step) : 0.0f;
    float negloinv = -lo * invstep;

    // walk this thread's phase-A index sequence IN REVERSE (L1 + L2 hot)
    int k = (n4 - 1 - base) / S;
    i = base + k * S;
    for (; i - S >= base; i -= 2 * S) {
        float4 v0 = s4[i];
        float4 v1 = s4[i - S];
        hist4(v0, sh, invstep, negloinv);
        hist4(v1, sh, invstep, negloinv);
    }
    for (; i >= base; i -= S) {
        float4 v0 = s4[i];
        hist4(v0, sh, invstep, negloinv);
    }
    if (t == 0 && (bid == 0 || bid == HALF)) {   // scalar tails into own hist
        const float* s = which ? b : a;
        for (int kk = (n4 << 2); kk < n; ++kk)
            atomicAdd(&sh[binof(s[kk], invstep, negloinv)], 1u);
    }
    __syncthreads();
    if (t == 0) sh[NX - 1] += sh[NX];            // fold bin 1000 -> 999
    __syncthreads();
    if (t < NX) atomicAdd(&g_hist[which][t], sh[t]);
    __syncthreads();

    // ---------------- last-arriving block: scan + trapz + reset -------------
    if (t == 0) {
        __threadfence();
        s_last = (atomicAdd(&g_ticket, 1u) == HB - 1u) ? 1u : 0u;
    }
    __syncthreads();
    if (!s_last) return;
    __threadfence();

    // 1 bin per thread (NX <= HT)
    unsigned int c0 = (t < NX) ? __ldcg(&g_hist[0][t]) : 0u;
    unsigned int c1 = (t < NX) ? __ldcg(&g_hist[1][t]) : 0u;
    unsigned int ic = c0, id = c1;
    #pragma unroll
    for (int o = 1; o < 32; o <<= 1) {
        unsigned int u0 = __shfl_up_sync(0xFFFFFFFFu, ic, o);
        unsigned int u1 = __shfl_up_sync(0xFFFFFFFFu, id, o);
        if (lane >= o) { ic += u0; id += u1; }
    }
    if (lane == 31) { ws0[w] = ic; ws1[w] = id; }
    __syncthreads();
    if (w == 0) {
        unsigned int v0 = ws0[lane], v1 = ws1[lane];
        #pragma unroll
        for (int o = 1; o < 32; o <<= 1) {
            unsigned int u0 = __shfl_up_sync(0xFFFFFFFFu, v0, o);
            unsigned int u1 = __shfl_up_sync(0xFFFFFFFFu, v1, o);
            if (lane >= o) { v0 += u0; v1 += u1; }
        }
        ws0[lane] = v0; ws1[lane] = v1;
    }
    __syncthreads();
    if (w > 0) { ic += ws0[w - 1]; id += ws1[w - 1]; }
    if (t < NX) { sh[t] = ic; sh2[t] = id; }
    __syncthreads();

    // trapz over 999 intervals, f32 term rounding matches reference
    float nf = (float)n;
    double acc = 0.0;
    if (t < NX - 1) {
        float cp0 = (float)sh[t] / nf;
        float ct0 = (float)sh2[t] / nf;
        float cp1 = (float)sh[t + 1] / nf;
        float ct1 = (float)sh2[t + 1] / nf;
        float y0 = cp0 - ct0; y0 = y0 * y0;
        float y1 = cp1 - ct1; y1 = y1 * y1;
        float dx = xval(t + 1, lo, hi, step) - xval(t, lo, hi, step);
        acc = (double)(0.5f * (y0 + y1) * dx);
    }
    for (int o = 16; o; o >>= 1)
        acc += __shfl_xor_sync(0xFFFFFFFFu, acc, o);
    if (lane == 0) sd[w] = acc;
    __syncthreads();
    if (t == 0) {
        double s = 0.0;
        #pragma unroll
        for (int q = 0; q < 32; ++q) s += sd[q];
        out[0] = (float)s;
    }

    // ---- reset all device state for the next graph replay ----
    __syncthreads();
    for (int i3 = t; i3 < 2 * NX; i3 += HT)
        ((unsigned int*)g_hist)[i3] = 0u;
    if (t == 0) {
        g_negmin_bits = 0u;
        g_max_bits = 0u;
        g_ticket = 0u;
        g_bar = 0u;
    }
}

// ---------------- launch ----------------------------------------------------
extern "C" void kernel_launch(void* const* d_in, const int* in_sizes, int n_in,
                              void* d_out, int out_size) {
    const float* p = (const float*)d_in[0];
    const float* tg = (const float*)d_in[1];
    int n = in_sizes[0];

    crps_k<<<HB, HT>>>(p, tg, n, (float*)d_out);
}